// round 15
// baseline (speedup 1.0000x reference)
#include <cuda_runtime.h>
#include <cuda_fp16.h>
#include <cstdint>

#define BS_  8
#define N_   4096
#define B_   8
#define R_   64
#define D_   256

#define MTILE   128
#define THREADS 128
#define ROWQ    144        // q/K smem row stride (64 fp16 data + 8 pad)
#define ROWB    272        // V smem row stride (128 fp16 data + 8 pad)
#define NTILES  2048       // total work items (64 pairs x 16 tiles... = 64*32? no: 4096/128)
#define GRID    760        // persistent CTAs: 5 per SM on 148-152 SMs

#define KV_ELEMS (BS_*B_*R_*D_)   // 1,048,576

// ---- smem layout (bytes) ----
#define SMO_Q    0                      // q chunk fp16 [128][72]  = 18432
#define SMO_K    18432                  // K chunk fp16 [64][72]   = 9216 (ends 27648)
#define SMO_V0   0                      // V chunk0 [64][136] = 17408 (overlays Q)
#define SMO_V1   17408                  // V chunk1 [64][136] = 17408 (ends 34816)
#define SMO_PART 34816                  // 128 rows x 4 chunks floats = 2048
#define SMO_INV  36864                  // 128 floats
#define SMO_TILE 37376                  // 4 bytes: stolen tile index
#define SMEM_TOTAL 37504

// Pre-converted K and a*V (fp16), written by the prelude kernel.
__device__ __half g_Kf[KV_ELEMS];
__device__ __half g_Vf[KV_ELEMS];
__device__ unsigned int g_tileCtr;

// Fast prelude: one float4 of K and V per thread; block 0 resets the work counter.
__global__ __launch_bounds__(256)
void ProceduralMemory_81535659147884_cvt(const float* __restrict__ K,
                                         const float* __restrict__ V,
                                         const float* __restrict__ a)
{
    if (blockIdx.x == 0 && threadIdx.x == 0) g_tileCtr = 0;
    const int idx = blockIdx.x * 256 + threadIdx.x;      // per float4
    const float4 k4 = ((const float4*)K)[idx];
    const float4 v4 = ((const float4*)V)[idx];
    const float av = a[idx / (D_ / 4)];
    uint2 kh, vh;
    __half2 t;
    t = __floats2half2_rn(k4.x, k4.y); kh.x = *(uint32_t*)&t;
    t = __floats2half2_rn(k4.z, k4.w); kh.y = *(uint32_t*)&t;
    t = __floats2half2_rn(v4.x * av, v4.y * av); vh.x = *(uint32_t*)&t;
    t = __floats2half2_rn(v4.z * av, v4.w * av); vh.y = *(uint32_t*)&t;
    ((uint2*)g_Kf)[idx] = kh;
    ((uint2*)g_Vf)[idx] = vh;
}

__device__ __forceinline__ uint32_t smem_u32(const void* p) {
    uint32_t a;
    asm("{ .reg .u64 t; cvta.to.shared.u64 t, %1; cvt.u32.u64 %0, t; }" : "=r"(a) : "l"(p));
    return a;
}
__device__ __forceinline__ void cpa16(uint32_t dst, const void* src) {
    asm volatile("cp.async.cg.shared.global [%0], [%1], 16;" :: "r"(dst), "l"(src));
}
__device__ __forceinline__ void ldsm4(uint32_t* r, uint32_t addr) {
    asm volatile("ldmatrix.sync.aligned.m8n8.x4.shared.b16 {%0,%1,%2,%3}, [%4];"
                 : "=r"(r[0]), "=r"(r[1]), "=r"(r[2]), "=r"(r[3]) : "r"(addr));
}
__device__ __forceinline__ void ldsm4t(uint32_t* r, uint32_t addr) {
    asm volatile("ldmatrix.sync.aligned.m8n8.x4.trans.shared.b16 {%0,%1,%2,%3}, [%4];"
                 : "=r"(r[0]), "=r"(r[1]), "=r"(r[2]), "=r"(r[3]) : "r"(addr));
}
__device__ __forceinline__ void mma16816(float* c, const uint32_t* a, const uint32_t* b) {
    asm volatile("mma.sync.aligned.m16n8k16.row.col.f32.f16.f16.f32 "
                 "{%0,%1,%2,%3}, {%4,%5,%6,%7}, {%8,%9}, {%0,%1,%2,%3};"
                 : "+f"(c[0]), "+f"(c[1]), "+f"(c[2]), "+f"(c[3])
                 : "r"(a[0]), "r"(a[1]), "r"(a[2]), "r"(a[3]), "r"(b[0]), "r"(b[1]));
}
__device__ __forceinline__ uint32_t packh2(float x, float y) {
    __half2 h = __floats2half2_rn(x, y);
    return *(uint32_t*)&h;
}
__device__ __forceinline__ void cvt4h(float4 v, uint2& hi) {
    __half hx = __float2half_rn(v.x), hy = __float2half_rn(v.y);
    __half hz = __float2half_rn(v.z), hw = __float2half_rn(v.w);
    hi.x = (uint32_t)__half_as_ushort(hx) | ((uint32_t)__half_as_ushort(hy) << 16);
    hi.y = (uint32_t)__half_as_ushort(hz) | ((uint32_t)__half_as_ushort(hw) << 16);
}

__global__ __launch_bounds__(THREADS, 5)
void ProceduralMemory_81535659147884_kernel(
    const float* __restrict__ q,
    float* __restrict__ out)
{
    extern __shared__ char smc[];
    const uint32_t smb = smem_u32(smc);

    const int tid  = threadIdx.x;
    const int wid  = tid >> 5;        // 0..3
    const int lane = tid & 31;

    float* partS = (float*)(smc + SMO_PART);
    float* invS  = (float*)(smc + SMO_INV);

    // ldsm base offsets (A: 32-row warp tile; B: K rows; V: trans)
    const uint32_t aOff = (uint32_t)(32 * wid + (lane & 15)) * ROWQ +
                          (uint32_t)(lane >> 4) * 16u;
    const uint32_t bOff = (uint32_t)((lane & 7) + ((lane & 16) >> 1)) * ROWQ +
                          (uint32_t)((lane >> 3) & 1) * 16u;
    const uint32_t vOff = (uint32_t)(lane & 15) * ROWB + (uint32_t)(lane >> 4) * 16u;

    while (true) {
        // ---- steal a tile (sync also fences previous iteration's smem reads) ----
        if (tid == 0)
            *(unsigned int*)(smc + SMO_TILE) = atomicAdd(&g_tileCtr, 1u);
        __syncthreads();
        const unsigned int t = *(const unsigned int*)(smc + SMO_TILE);
        if (t >= NTILES) return;

        const int pair = (int)(t >> 5);          // 0..63 (32 tiles per pair)
        const int tile = (int)(t & 31);          // 0..31
        const int s = pair >> 3, b = pair & 7;
        const int n0 = tile * MTILE;

        // GEMM1 accumulators: warp tile 32 rows x 64 n, persist over 4 K-chunks
        float acc[2][8][4];
        #pragma unroll
        for (int mt = 0; mt < 2; ++mt)
            #pragma unroll
            for (int nt = 0; nt < 8; ++nt)
                #pragma unroll
                for (int i = 0; i < 4; ++i) acc[mt][nt][i] = 0.f;

        #pragma unroll 1
        for (int c = 0; c < 4; ++c) {
            if (c > 0) __syncthreads();   // previous chunk done reading Q/K

            // ---- Issue K chunk cp.async (flies under the q work below) ----
            {
                const __half* ks = g_Kf + (size_t)pair * (R_ * D_) + c * 64;
                #pragma unroll
                for (int g = 0; g < 4; ++g) {
                    const int idx = g * 128 + tid;        // 0..511
                    const int r = idx >> 3, gc = idx & 7;
                    cpa16(smb + SMO_K + (uint32_t)r * ROWQ + (uint32_t)gc * 16u,
                          ks + (size_t)r * D_ + gc * 8);
                }
                asm volatile("cp.async.commit_group;" ::: "memory");
            }

            // ---- Load q chunk [128 rows, cols 64c..], cvt fp16, ssq partials ----
            {
                const float4* qg = (const float4*)q;
                #pragma unroll 4
                for (int p = 0; p < 16; ++p) {
                    const int m = 32 * wid + 2 * p + (lane >> 4);
                    const int f4 = lane & 15;
                    float4 v = qg[((size_t)(s * N_ + n0 + m) * B_ + b) * 64 + c * 16 + f4];
                    float ss = v.x * v.x + v.y * v.y + v.z * v.z + v.w * v.w;
                    #pragma unroll
                    for (int o = 8; o; o >>= 1) ss += __shfl_xor_sync(0xFFFFFFFFu, ss, o);
                    if ((lane & 15) == 0) partS[m * 4 + c] = ss;
                    uint2 hi; cvt4h(v, hi);
                    *(uint2*)(smc + SMO_Q + (uint32_t)m * ROWQ + (uint32_t)f4 * 8u) = hi;
                }
            }
            asm volatile("cp.async.wait_group 0;" ::: "memory");
            __syncthreads();

            if (c == 3) {
                const float ss = partS[tid * 4] + partS[tid * 4 + 1] +
                                 partS[tid * 4 + 2] + partS[tid * 4 + 3];
                invS[tid] = 1.0f / fmaxf(sqrtf(ss), 1e-8f);
            }

            // ---- GEMM1 partial over this 64-col chunk (4 k-steps) ----
            #pragma unroll
            for (int k = 0; k < 4; ++k) {
                uint32_t a0[4], a1[4];
                ldsm4(a0, smb + SMO_Q + aOff + (uint32_t)k * 32u);
                ldsm4(a1, smb + SMO_Q + aOff + 16u * ROWQ + (uint32_t)k * 32u);
                #pragma unroll
                for (int g = 0; g < 4; ++g) {
                    uint32_t bb[4];
                    ldsm4(bb, smb + SMO_K + bOff + (uint32_t)g * (16u * ROWQ) +
                              (uint32_t)k * 32u);
                    mma16816(acc[0][2 * g + 0], a0, bb + 0);
                    mma16816(acc[0][2 * g + 1], a0, bb + 2);
                    mma16816(acc[1][2 * g + 0], a1, bb + 0);
                    mma16816(acc[1][2 * g + 1], a1, bb + 2);
                }
            }
        }
        __syncthreads();   // GEMM1 done reading Q/K; invS visible below

        // ---- Issue BOTH V chunks: V0 -> SMO_V0, V1 -> SMO_V1 (two groups) ----
        {
            const __half* vs = g_Vf + (size_t)pair * (R_ * D_);
            #pragma unroll
            for (int g = 0; g < 8; ++g) {
                const int idx = g * 128 + tid;
                const int r = idx >> 4, gc = idx & 15;
                cpa16(smb + SMO_V0 + (uint32_t)r * ROWB + (uint32_t)gc * 16u,
                      vs + (size_t)r * D_ + gc * 8);
            }
            asm volatile("cp.async.commit_group;" ::: "memory");
            #pragma unroll
            for (int g = 0; g < 8; ++g) {
                const int idx = g * 128 + tid;
                const int r = idx >> 4, gc = idx & 15;
                cpa16(smb + SMO_V1 + (uint32_t)r * ROWB + (uint32_t)gc * 16u,
                      vs + (size_t)r * D_ + 128 + gc * 8);
            }
            asm volatile("cp.async.commit_group;" ::: "memory");
        }

        // ---- Epilogue1 (registers only, overlaps V copies):
        //      w = score * inv -> fp16 A-fragments whi[2][4][4] ----
        uint32_t whi[2][4][4];
        #pragma unroll
        for (int mt = 0; mt < 2; ++mt) {
            const int r0 = 32 * wid + 16 * mt + (lane >> 2);
            const float inv0 = invS[r0], inv1 = invS[r0 + 8];
            #pragma unroll
            for (int kt = 0; kt < 4; ++kt) {
                whi[mt][kt][0] = packh2(acc[mt][2 * kt][0] * inv0,
                                        acc[mt][2 * kt][1] * inv0);
                whi[mt][kt][1] = packh2(acc[mt][2 * kt][2] * inv1,
                                        acc[mt][2 * kt][3] * inv1);
                whi[mt][kt][2] = packh2(acc[mt][2 * kt + 1][0] * inv0,
                                        acc[mt][2 * kt + 1][1] * inv0);
                whi[mt][kt][3] = packh2(acc[mt][2 * kt + 1][2] * inv1,
                                        acc[mt][2 * kt + 1][3] * inv1);
            }
        }

        // ============ GEMM2: mod[128,256] = W . (a*V); 8 sub-chunks of 32 cols ============
        #pragma unroll 1
        for (int j = 0; j < 2; ++j) {
            if (j == 0) {
                asm volatile("cp.async.wait_group 1;" ::: "memory");  // V0 landed
            } else {
                asm volatile("cp.async.wait_group 0;" ::: "memory");  // V1 landed
            }
            __syncthreads();

            const uint32_t vBase = smb + (j == 0 ? SMO_V0 : SMO_V1) + vOff;

            #pragma unroll 1
            for (int sub = 0; sub < 4; ++sub) {     // 32 output cols at a time
                float acc2[2][4][4];
                #pragma unroll
                for (int mt = 0; mt < 2; ++mt)
                    #pragma unroll
                    for (int nt = 0; nt < 4; ++nt)
                        #pragma unroll
                        for (int i = 0; i < 4; ++i) acc2[mt][nt][i] = 0.f;

                #pragma unroll
                for (int k = 0; k < 4; ++k) {
                    #pragma unroll
                    for (int g = 0; g < 2; ++g) {
                        uint32_t bb[4];
                        ldsm4t(bb, vBase + (uint32_t)k * (16u * ROWB) +
                                   (uint32_t)sub * 64u + (uint32_t)g * 32u);
                        mma16816(acc2[0][2 * g + 0], whi[0][k], bb + 0);
                        mma16816(acc2[0][2 * g + 1], whi[0][k], bb + 2);
                        mma16816(acc2[1][2 * g + 0], whi[1][k], bb + 0);
                        mma16816(acc2[1][2 * g + 1], whi[1][k], bb + 2);
                    }
                }

                // ---- Epilogue2: out = q * mod (q re-read from gmem, L2-resident) ----
                const int colb = 128 * j + 32 * sub + 2 * (lane & 3);
                #pragma unroll
                for (int mt = 0; mt < 2; ++mt) {
                    #pragma unroll
                    for (int h = 0; h < 2; ++h) {
                        const int m = 32 * wid + 16 * mt + (lane >> 2) + 8 * h;
                        const size_t gbase = ((size_t)(s * N_ + n0 + m) * B_ + b) * D_;
                        #pragma unroll
                        for (int nt = 0; nt < 4; ++nt) {
                            const int col = colb + 8 * nt;
                            float2 qv = *(const float2*)(q + gbase + col);
                            float2 o;
                            o.x = qv.x * acc2[mt][nt][2 * h];
                            o.y = qv.y * acc2[mt][nt][2 * h + 1];
                            *(float2*)(out + gbase + col) = o;
                        }
                    }
                }
            }
        }
    }
}

extern "C" void kernel_launch(void* const* d_in, const int* in_sizes, int n_in,
                              void* d_out, int out_size)
{
    const float* q    = (const float*)d_in[0];
    const float* pm_K = (const float*)d_in[1];
    const float* pm_V = (const float*)d_in[2];
    const float* pm_a = (const float*)d_in[3];
    float* out = (float*)d_out;

    cudaFuncSetAttribute(ProceduralMemory_81535659147884_kernel,
                         cudaFuncAttributeMaxDynamicSharedMemorySize, SMEM_TOTAL);

    // Prelude: convert K -> fp16, a*V -> fp16 into device scratch; resets work counter.
    ProceduralMemory_81535659147884_cvt<<<KV_ELEMS / 1024, 256>>>(pm_K, pm_V, pm_a);

    // Persistent CTAs with atomic work-stealing over 2048 tiles of 128 rows.
    ProceduralMemory_81535659147884_kernel<<<GRID, THREADS, SMEM_TOTAL>>>(q, out);
}

// round 16
// speedup vs baseline: 1.2622x; 1.2622x over previous
#include <cuda_runtime.h>
#include <cuda_fp16.h>
#include <cstdint>

#define BS_  8
#define N_   4096
#define B_   8
#define R_   64
#define D_   256

#define MTILE   64
#define THREADS 128
#define ROWB    272        // bytes per smem row: 136 fp16 (128 data + 8 pad)
#define NTILES  4096       // total work items
#define GRID    760        // persistent CTAs: 5 per SM on 148-152 SMs

#define KV_ELEMS (BS_*B_*R_*D_)   // 1,048,576

// ---- smem layout (bytes) ----
#define SMO_AHI  0                      // q chunk fp16 [64][136] = 17408 (later V0)
#define SMO_BB   17408                  // K chunk fp16 [64][136]         (later V1)
#define SMO_PART 34816                  // 256 floats: ssq partials [64][2 chunks][2 halves]
#define SMO_INV  35840                  // 64 floats
#define SMO_TILE 36096                  // 4 bytes: stolen tile index
#define SMEM_TOTAL 36224

// Pre-converted K and a*V (fp16), written by the prelude kernel.
__device__ __half g_Kf[KV_ELEMS];
__device__ __half g_Vf[KV_ELEMS];
__device__ unsigned int g_tileCtr;

// Fast prelude: one float4 of K and V per thread; block 0 resets the work counter.
__global__ __launch_bounds__(256)
void ProceduralMemory_81535659147884_cvt(const float* __restrict__ K,
                                         const float* __restrict__ V,
                                         const float* __restrict__ a)
{
    if (blockIdx.x == 0 && threadIdx.x == 0) g_tileCtr = 0;
    const int idx = blockIdx.x * 256 + threadIdx.x;      // per float4
    const float4 k4 = ((const float4*)K)[idx];
    const float4 v4 = ((const float4*)V)[idx];
    const float av = a[idx / (D_ / 4)];
    uint2 kh, vh;
    __half2 t;
    t = __floats2half2_rn(k4.x, k4.y); kh.x = *(uint32_t*)&t;
    t = __floats2half2_rn(k4.z, k4.w); kh.y = *(uint32_t*)&t;
    t = __floats2half2_rn(v4.x * av, v4.y * av); vh.x = *(uint32_t*)&t;
    t = __floats2half2_rn(v4.z * av, v4.w * av); vh.y = *(uint32_t*)&t;
    ((uint2*)g_Kf)[idx] = kh;
    ((uint2*)g_Vf)[idx] = vh;
}

__device__ __forceinline__ uint32_t smem_u32(const void* p) {
    uint32_t a;
    asm("{ .reg .u64 t; cvta.to.shared.u64 t, %1; cvt.u32.u64 %0, t; }" : "=r"(a) : "l"(p));
    return a;
}
__device__ __forceinline__ void cpa16(uint32_t dst, const void* src) {
    asm volatile("cp.async.cg.shared.global [%0], [%1], 16;" :: "r"(dst), "l"(src));
}
__device__ __forceinline__ void ldsm4(uint32_t* r, uint32_t addr) {
    asm volatile("ldmatrix.sync.aligned.m8n8.x4.shared.b16 {%0,%1,%2,%3}, [%4];"
                 : "=r"(r[0]), "=r"(r[1]), "=r"(r[2]), "=r"(r[3]) : "r"(addr));
}
__device__ __forceinline__ void ldsm4t(uint32_t* r, uint32_t addr) {
    asm volatile("ldmatrix.sync.aligned.m8n8.x4.trans.shared.b16 {%0,%1,%2,%3}, [%4];"
                 : "=r"(r[0]), "=r"(r[1]), "=r"(r[2]), "=r"(r[3]) : "r"(addr));
}
__device__ __forceinline__ void mma16816(float* c, const uint32_t* a, const uint32_t* b) {
    asm volatile("mma.sync.aligned.m16n8k16.row.col.f32.f16.f16.f32 "
                 "{%0,%1,%2,%3}, {%4,%5,%6,%7}, {%8,%9}, {%0,%1,%2,%3};"
                 : "+f"(c[0]), "+f"(c[1]), "+f"(c[2]), "+f"(c[3])
                 : "r"(a[0]), "r"(a[1]), "r"(a[2]), "r"(a[3]), "r"(b[0]), "r"(b[1]));
}
__device__ __forceinline__ uint32_t packh2(float x, float y) {
    __half2 h = __floats2half2_rn(x, y);
    return *(uint32_t*)&h;
}
__device__ __forceinline__ void cvt4h(float4 v, uint2& hi) {
    __half hx = __float2half_rn(v.x), hy = __float2half_rn(v.y);
    __half hz = __float2half_rn(v.z), hw = __float2half_rn(v.w);
    hi.x = (uint32_t)__half_as_ushort(hx) | ((uint32_t)__half_as_ushort(hy) << 16);
    hi.y = (uint32_t)__half_as_ushort(hz) | ((uint32_t)__half_as_ushort(hw) << 16);
}

__global__ __launch_bounds__(THREADS, 5)
void ProceduralMemory_81535659147884_kernel(
    const float* __restrict__ q,
    float* __restrict__ out)
{
    extern __shared__ char smc[];
    const uint32_t smb = smem_u32(smc);

    const int tid  = threadIdx.x;
    const int wid  = tid >> 5;        // 0..3
    const int lane = tid & 31;

    float* partS = (float*)(smc + SMO_PART);
    float* invS  = (float*)(smc + SMO_INV);

    const uint32_t aOff = (uint32_t)(16 * wid + (lane & 15)) * ROWB +
                          (uint32_t)(lane >> 4) * 16u;
    const uint32_t bOff = (uint32_t)((lane & 7) + ((lane & 16) >> 1)) * ROWB +
                          (uint32_t)((lane >> 3) & 1) * 16u;
    const uint32_t vOff = (uint32_t)(lane & 15) * ROWB + (uint32_t)(lane >> 4) * 16u;

    while (true) {
        // ---- steal a tile (sync also fences previous iteration's smem reads) ----
        if (tid == 0)
            *(unsigned int*)(smc + SMO_TILE) = atomicAdd(&g_tileCtr, 1u);
        __syncthreads();
        const unsigned int t = *(const unsigned int*)(smc + SMO_TILE);
        if (t >= NTILES) return;

        const int pair = (int)(t >> 6);          // 0..63
        const int tile = (int)(t & 63);          // 0..63
        const int s = pair >> 3, b = pair & 7;
        const int n0 = tile * MTILE;

        // GEMM1 accumulators: warp tile 16 rows x 64 n, persist over 2 K-chunks
        float acc[8][4];
        #pragma unroll
        for (int nt = 0; nt < 8; ++nt)
            #pragma unroll
            for (int i = 0; i < 4; ++i) acc[nt][i] = 0.f;

        #pragma unroll 1
        for (int c = 0; c < 2; ++c) {
            if (c > 0) __syncthreads();   // GEMM1 chunk0 done reading buffers

            // ---- Issue K chunk cp.async first (flies under the q work below) ----
            {
                const __half* ks = g_Kf + (size_t)pair * (R_ * D_) + c * 128;
                #pragma unroll
                for (int g = 0; g < 8; ++g) {
                    const int idx = g * 128 + tid;        // 0..1023
                    const int r = idx >> 4, gc = idx & 15;
                    cpa16(smb + SMO_BB + (uint32_t)r * ROWB + (uint32_t)gc * 16u,
                          ks + (size_t)r * D_ + gc * 8);
                }
                asm volatile("cp.async.commit_group;" ::: "memory");
            }

            // ---- Load q chunk [64 rows, cols 128c..], cvt fp16, ssq partials ----
            {
                const float4* qg = (const float4*)q;
                #pragma unroll 4
                for (int rr = 0; rr < 16; ++rr) {
                    const int m = 16 * wid + rr;
                    float4 v = qg[((size_t)(s * N_ + n0 + m) * B_ + b) * 64 + c * 32 + lane];
                    float ss = v.x * v.x + v.y * v.y + v.z * v.z + v.w * v.w;
                    // depth-4 butterfly: lanes 0 and 16 hold their 16-lane half-sums
                    #pragma unroll
                    for (int o = 8; o; o >>= 1) ss += __shfl_xor_sync(0xFFFFFFFFu, ss, o);
                    if ((lane & 15) == 0) partS[m * 4 + c * 2 + (lane >> 4)] = ss;
                    uint2 hi; cvt4h(v, hi);
                    *(uint2*)(smc + SMO_AHI + (uint32_t)m * ROWB + (uint32_t)lane * 8u) = hi;
                }
            }
            asm volatile("cp.async.wait_group 0;" ::: "memory");
            __syncthreads();

            if (c == 1 && tid < MTILE) {
                const float ss = partS[tid * 4 + 0] + partS[tid * 4 + 1] +
                                 partS[tid * 4 + 2] + partS[tid * 4 + 3];
                invS[tid] = 1.0f / fmaxf(sqrtf(ss), 1e-8f);
            }

            // ---- GEMM1 partial: pure fp16, 1 pass per k-step ----
            #pragma unroll
            for (int k = 0; k < 8; ++k) {
                uint32_t ah[4];
                ldsm4(ah, smb + SMO_AHI + aOff + (uint32_t)k * 32u);
                #pragma unroll
                for (int g = 0; g < 4; ++g) {
                    uint32_t bb[4];
                    ldsm4(bb, smb + SMO_BB + bOff + (uint32_t)g * (16u * ROWB) +
                              (uint32_t)k * 32u);
                    mma16816(acc[2 * g + 0], ah, bb + 0);
                    mma16816(acc[2 * g + 1], ah, bb + 2);
                }
            }
        }
        __syncthreads();   // GEMM1 done reading AHI/BB; invS visible below

        // ---- Issue BOTH V chunks now: V0 -> AHI, V1 -> BB (two commit groups) ----
        {
            const __half* vs = g_Vf + (size_t)pair * (R_ * D_);
            #pragma unroll
            for (int g = 0; g < 8; ++g) {
                const int idx = g * 128 + tid;
                const int r = idx >> 4, gc = idx & 15;
                cpa16(smb + SMO_AHI + (uint32_t)r * ROWB + (uint32_t)gc * 16u,
                      vs + (size_t)r * D_ + gc * 8);
            }
            asm volatile("cp.async.commit_group;" ::: "memory");
            #pragma unroll
            for (int g = 0; g < 8; ++g) {
                const int idx = g * 128 + tid;
                const int r = idx >> 4, gc = idx & 15;
                cpa16(smb + SMO_BB + (uint32_t)r * ROWB + (uint32_t)gc * 16u,
                      vs + (size_t)r * D_ + 128 + gc * 8);
            }
            asm volatile("cp.async.commit_group;" ::: "memory");
        }

        // ---- Epilogue1 (registers only, overlaps V copies):
        //      w = score * inv -> fp16 A-fragments ----
        uint32_t whi[4][4];
        {
            const int r0 = 16 * wid + (lane >> 2);
            const float inv0 = invS[r0], inv1 = invS[r0 + 8];
            #pragma unroll
            for (int kt = 0; kt < 4; ++kt) {
                #pragma unroll
                for (int hf = 0; hf < 2; ++hf) {
                    const int nt = 2 * kt + hf;
                    whi[kt][2 * hf + 0] = packh2(acc[nt][0] * inv0, acc[nt][1] * inv0);
                    whi[kt][2 * hf + 1] = packh2(acc[nt][2] * inv1, acc[nt][3] * inv1);
                }
            }
        }

        // ============ GEMM2: mod[64,256] = W . (a*V); V0 in AHI, V1 in BB ============
        #pragma unroll 1
        for (int j = 0; j < 2; ++j) {
            if (j == 0) {
                asm volatile("cp.async.wait_group 1;" ::: "memory");  // V0 landed
            } else {
                asm volatile("cp.async.wait_group 0;" ::: "memory");  // V1 landed
            }
            __syncthreads();   // cross-thread visibility of the V chunk

            const uint32_t vBase = smb + (j == 0 ? SMO_AHI : SMO_BB) + vOff;

            #pragma unroll 1
            for (int sub = 0; sub < 2; ++sub) {     // 64 output cols at a time
                float acc2[8][4];
                #pragma unroll
                for (int nt = 0; nt < 8; ++nt)
                    #pragma unroll
                    for (int i = 0; i < 4; ++i) acc2[nt][i] = 0.f;

                #pragma unroll
                for (int k = 0; k < 4; ++k) {
                    #pragma unroll
                    for (int g = 0; g < 4; ++g) {
                        uint32_t bb[4];
                        ldsm4t(bb, vBase + (uint32_t)k * (16u * ROWB) +
                                   (uint32_t)sub * 128u + (uint32_t)g * 32u);
                        mma16816(acc2[2 * g + 0], whi[k], bb + 0);
                        mma16816(acc2[2 * g + 1], whi[k], bb + 2);
                    }
                }

                // ---- Epilogue2: out = q * mod (q re-read from gmem, L2-resident) ----
                #pragma unroll
                for (int h = 0; h < 2; ++h) {
                    const int m = 16 * wid + (lane >> 2) + 8 * h;
                    const size_t gbase = ((size_t)(s * N_ + n0 + m) * B_ + b) * D_;
                    #pragma unroll
                    for (int nt = 0; nt < 8; ++nt) {
                        const int col = 128 * j + 64 * sub + 8 * nt + 2 * (lane & 3);
                        float2 qv = *(const float2*)(q + gbase + col);
                        float2 o;
                        o.x = qv.x * acc2[nt][2 * h];
                        o.y = qv.y * acc2[nt][2 * h + 1];
                        *(float2*)(out + gbase + col) = o;
                    }
                }
            }
        }
    }
}

extern "C" void kernel_launch(void* const* d_in, const int* in_sizes, int n_in,
                              void* d_out, int out_size)
{
    const float* q    = (const float*)d_in[0];
    const float* pm_K = (const float*)d_in[1];
    const float* pm_V = (const float*)d_in[2];
    const float* pm_a = (const float*)d_in[3];
    float* out = (float*)d_out;

    cudaFuncSetAttribute(ProceduralMemory_81535659147884_kernel,
                         cudaFuncAttributeMaxDynamicSharedMemorySize, SMEM_TOTAL);

    // Prelude: convert K -> fp16, a*V -> fp16 into device scratch; resets work counter.
    ProceduralMemory_81535659147884_cvt<<<KV_ELEMS / 1024, 256>>>(pm_K, pm_V, pm_a);

    // Persistent CTAs with atomic work-stealing over 4096 tiles.
    ProceduralMemory_81535659147884_kernel<<<GRID, THREADS, SMEM_TOTAL>>>(q, out);
}